// round 16
// baseline (speedup 1.0000x reference)
#include <cuda_runtime.h>
#include <cuda_fp16.h>
#include <cstdint>
#include <cstddef>

// Problem constants
#define B_  2
#define S_  400
#define SP_ 416                         // S padded to 2x208 (208 % 16 == 0)
#define D_  512
#define ROWS (B_ * S_)                  // 800
#define ALIGN_OFF (S_ * B_ * D_)        // 409600
#define NBLK 148

// Scratch (device globals: no allocation allowed)
__device__ __half g_wq_h[ROWS * D_];
__device__ __half g_uh_h[ROWS * D_];
__device__ __half g_in_h[ROWS * D_];
__device__ __half g_mem_h[ROWS * D_];
__device__ __half g_memT_h[B_ * D_ * SP_];     // per b: [512][416], zero-padded
__device__ __half g_WqT[D_ * D_];              // [n][k]
__device__ __half g_WcT[D_ * D_];
__device__ __half g_WoutT[D_ * 2 * D_];        // [512][1024]
__device__ __half g_ctx_h[ROWS * D_];
__device__ __half g_align_h[S_ * B_ * SP_];    // [t][b][416], zero-padded

// Global barrier state (count always returns to 0; gen monotonic across replays)
__device__ unsigned g_cnt = 0;
__device__ unsigned g_gen = 0;

// ---------------------------------------------------------------------------
__device__ __forceinline__ __half2 tanh2_fast(__half2 x) {
    uint32_t xi = *(uint32_t*)&x, yi;
    asm("tanh.approx.f16x2 %0, %1;" : "=r"(yi) : "r"(xi));
    return *(__half2*)&yi;
}

__device__ __forceinline__ uint32_t smem_u32(const void* p) {
    uint32_t a;
    asm("{ .reg .u64 t; cvta.to.shared.u64 t, %1; cvt.u32.u64 %0, t; }"
        : "=r"(a) : "l"(p));
    return a;
}

#define MBAR_INIT(mbar, cnt) \
    asm volatile("mbarrier.init.shared.b64 [%0], %1;" \
        :: "r"((uint32_t)(mbar)), "r"((uint32_t)(cnt)) : "memory")

#define MBAR_WAIT(mbar, parity) do { \
    uint32_t _m = (uint32_t)(mbar); uint32_t _p = (uint32_t)(parity); uint32_t _d; \
    asm volatile("{\n\t.reg .pred p;\n\t" \
        "mbarrier.try_wait.parity.acquire.cta.shared::cta.b64 p, [%1], %2;\n\t" \
        "selp.b32 %0, 1, 0, p;\n\t}" : "=r"(_d) : "r"(_m), "r"(_p) : "memory"); \
    if (!_d) { \
        asm volatile("{\n\t.reg .pred P1;\n\t" \
            "WL_%=:\n\t" \
            "mbarrier.try_wait.parity.acquire.cta.shared::cta.b64 P1, [%0], %1, 0x989680;\n\t" \
            "@P1 bra.uni WD_%=;\n\t" \
            "bra.uni WL_%=;\n\t" \
            "WD_%=:\n\t}" :: "r"(_m), "r"(_p) : "memory"); \
    } \
} while (0)

__device__ __forceinline__ void bulk_cp(uint32_t dst, const void* src,
                                        uint32_t bytes, uint32_t mbar) {
    asm volatile(
        "cp.async.bulk.shared::cluster.global.mbarrier::complete_tx::bytes "
        "[%0], [%1], %2, [%3];"
        :: "r"(dst), "l"(src), "r"(bytes), "r"(mbar) : "memory");
}

__device__ __forceinline__ void ldsm_x4(uint32_t* r, uint32_t addr) {
    asm volatile("ldmatrix.sync.aligned.m8n8.x4.shared.b16 {%0,%1,%2,%3}, [%4];"
                 : "=r"(r[0]), "=r"(r[1]), "=r"(r[2]), "=r"(r[3]) : "r"(addr));
}

__device__ __forceinline__ void mma16(float* d, const uint32_t* a,
                                      uint32_t b0, uint32_t b1) {
    asm volatile(
        "mma.sync.aligned.m16n8k16.row.col.f32.f16.f16.f32 "
        "{%0,%1,%2,%3}, {%4,%5,%6,%7}, {%8,%9}, {%0,%1,%2,%3};"
        : "+f"(d[0]), "+f"(d[1]), "+f"(d[2]), "+f"(d[3])
        : "r"(a[0]), "r"(a[1]), "r"(a[2]), "r"(a[3]), "r"(b0), "r"(b1));
}

// Sense-reversing grid barrier (all NBLK CTAs resident: 1 CTA/SM).
__device__ __forceinline__ void gbar() {
    __syncthreads();
    if (threadIdx.x == 0) {
        const unsigned gen = *(volatile unsigned*)&g_gen;
        __threadfence();
        if (atomicAdd(&g_cnt, 1u) == NBLK - 1u) {
            atomicExch(&g_cnt, 0u);
            __threadfence();
            atomicExch(&g_gen, gen + 1u);
        } else {
            while (*(volatile unsigned*)&g_gen == gen) { }
        }
        __threadfence();
    }
    __syncthreads();
}

// ---------------------------------------------------------------------------
struct GemmDesc {
    const __half* A;      // [M, KA] row-major, lda (halves)
    const __half* A2;     // [M, K-KA] row-major, lda (concat tail)
    const __half* Bt;     // [N, K] row-major, ldb  (B transposed)
    const float*  bias;   // [N] or null
    float*        C;      // f32 out (omode 0/1)
    __half*       Ch;     // f16 out (omode 2)
    int lda, KA, ldb, ldc, omode, M, K, KS, bufs;
};

// One 64x64 output tile: bulk-DMA double-buffered fp16 mma.sync (R14 config).
// gcnt/ph carry mbarrier usage parity across tiles and stages (per CTA).
__device__ void gemm_tile(char* sm, uint32_t mb, unsigned& gcnt, int* ph,
                          const GemmDesc& d, int row0, int col0)
{
    const int tid = threadIdx.x, warp = tid >> 5, lane = tid & 31;
    const int q = lane >> 2, r = lane & 3;
    const int wm = warp >> 2;                  // 0..1 : M offset 32*wm
    const int wn = warp & 3;                   // 0..3 : N offset 16*wn
    const int KS = d.KS, bufs = d.bufs;
    const int RS = KS + 8;
    const int ns = d.K / KS;
    const uint32_t shb = smem_u32(sm);
    const uint32_t boff = (uint32_t)bufs * 64u * (uint32_t)RS;   // halves

    const int  lrow  = tid & 63;
    const bool isA   = tid < 64;
    const bool isLd  = tid < 128;
    const int  arow_g = row0 + lrow;
    const int  arow_c = (arow_g < d.M) ? arow_g : (d.M - 1);
    const uint32_t stage_bytes = (uint32_t)KS * 2u * 128u;

    auto issue = [&](int c) {
        const int bi = c & (bufs - 1);
        const uint32_t mbar = mb + (((gcnt + (unsigned)c) & 1u) * 8u);
        if (tid == 0)
            asm volatile("mbarrier.arrive.expect_tx.shared.b64 _, [%0], %1;"
                         :: "r"(mbar), "r"(stage_bytes) : "memory");
        if (isLd) {
            const int k0 = c * KS;
            const __half* src;
            uint32_t dst;
            if (isA) {
                const __half* Ab = (k0 < d.KA) ? d.A : d.A2;
                const int kk = (k0 < d.KA) ? k0 : (k0 - d.KA);
                src = Ab + (size_t)arow_c * d.lda + kk;
                dst = shb + (uint32_t)((bi * 64 + lrow) * RS) * 2u;
            } else {
                src = d.Bt + (size_t)(col0 + lrow) * d.ldb + (size_t)c * KS;
                dst = shb + (boff + (uint32_t)((bi * 64 + lrow) * RS)) * 2u;
            }
            bulk_cp(dst, src, (uint32_t)KS * 2u, mbar);
        }
    };

    float acc[2][2][4];
    #pragma unroll
    for (int i = 0; i < 2; ++i)
        #pragma unroll
        for (int j2 = 0; j2 < 2; ++j2)
            #pragma unroll
            for (int k2 = 0; k2 < 4; ++k2) acc[i][j2][k2] = 0.f;

    issue(0);

    const int j   = lane & 7;
    const int sm8 = (lane >> 3) & 1;
    const int sk8 = (lane >> 4) & 1;

    for (int c = 0; c < ns; ++c) {
        if (c + 1 < ns) issue(c + 1);
        const int bix = (int)((gcnt + (unsigned)c) & 1u);
        MBAR_WAIT(mb + bix * 8, ph[bix]);
        ph[bix] ^= 1;

        const int bi = c & (bufs - 1);
        const uint32_t Ab = shb + (uint32_t)(bi * 64 * RS) * 2u;
        const uint32_t Bb = shb + (boff + (uint32_t)(bi * 64 * RS)) * 2u;
        const int steps = KS >> 4;

        const uint32_t arow_off = (uint32_t)((wm * 32 + j + 8 * sm8) * RS + 8 * sk8) * 2u;
        const uint32_t brow_off = (uint32_t)((wn * 16 + j + 8 * sm8) * RS + 8 * sk8) * 2u;

        for (int s = 0; s < steps; ++s) {
            const uint32_t kb2 = (uint32_t)(s * 16) * 2u;
            uint32_t a0[4], a1[4], bb[4];
            ldsm_x4(a0, Ab + arow_off + kb2);
            ldsm_x4(a1, Ab + arow_off + kb2 + (uint32_t)(16 * RS) * 2u);
            ldsm_x4(bb, Bb + brow_off + kb2);
            mma16(acc[0][0], a0, bb[0], bb[2]);
            mma16(acc[0][1], a0, bb[1], bb[3]);
            mma16(acc[1][0], a1, bb[0], bb[2]);
            mma16(acc[1][1], a1, bb[1], bb[3]);
        }
        __syncthreads();
    }
    gcnt += (unsigned)ns;

    // ---- epilogue ----
    float bv[2][2];
    #pragma unroll
    for (int nt = 0; nt < 2; ++nt) {
        const int cc = col0 + wn * 16 + nt * 8 + r * 2;
        bv[nt][0] = d.bias ? __ldg(d.bias + cc)     : 0.f;
        bv[nt][1] = d.bias ? __ldg(d.bias + cc + 1) : 0.f;
    }
    #pragma unroll
    for (int mt = 0; mt < 2; ++mt) {
        #pragma unroll
        for (int rh = 0; rh < 2; ++rh) {
            const int rr = row0 + wm * 32 + mt * 16 + rh * 8 + q;
            if (rr >= d.M) continue;
            #pragma unroll
            for (int nt = 0; nt < 2; ++nt) {
                const int cc = col0 + wn * 16 + nt * 8 + r * 2;
                const float ox = acc[mt][nt][rh * 2 + 0] + bv[nt][0];
                const float oy = acc[mt][nt][rh * 2 + 1] + bv[nt][1];
                if (d.omode == 2) {
                    __half2* dp = (__half2*)(d.Ch + (size_t)rr * d.ldc + cc);
                    *dp = __floats2half2_rn(ox, oy);
                } else {
                    float* rowp;
                    if (d.omode == 0) rowp = d.C + (size_t)rr * d.ldc;
                    else {
                        const int t = rr % S_, bbn = rr / S_;
                        rowp = d.C + (size_t)t * (B_ * D_) + (size_t)bbn * D_;
                    }
                    *(float2*)(rowp + cc) = make_float2(ox, oy);
                }
            }
        }
    }
}

// ---------------------------------------------------------------------------
// Prep unit (one 32x32 transpose tile, or one conv chunk). 1840 units total.
// ---------------------------------------------------------------------------
__device__ void prep_unit(char* sm, int blk,
    const float* input, const float* memory,
    const float* Wq, const float* Wc, const float* Wout)
{
    const int tid = threadIdx.x;

    if (blk >= 1440) {   // conv job
        const int i = (blk - 1440) * 256 + tid;      // < 102400 = ROWS*D_/4
        float4 vv = ((const float4*)input)[i];
        ((__half2*)g_in_h)[2 * i]     = __floats2half2_rn(vv.x, vv.y);
        ((__half2*)g_in_h)[2 * i + 1] = __floats2half2_rn(vv.z, vv.w);
        vv = ((const float4*)memory)[i];
        ((__half2*)g_mem_h)[2 * i]     = __floats2half2_rn(vv.x, vv.y);
        ((__half2*)g_mem_h)[2 * i + 1] = __floats2half2_rn(vv.z, vv.w);
        return;
    }

    const float* I; __half* O; int R, Rout, local;
    if (blk < 256)       { I = Wq;   O = g_WqT;   R = 512;  Rout = 512;  local = blk; }
    else if (blk < 512)  { I = Wc;   O = g_WcT;   R = 512;  Rout = 512;  local = blk - 256; }
    else if (blk < 1024) { I = Wout; O = g_WoutT; R = 1024; Rout = 1024; local = blk - 512; }
    else if (blk < 1232) { I = memory;             O = g_memT_h;             R = 400; Rout = SP_; local = blk - 1024; }
    else                 { I = memory + 400 * 512; O = g_memT_h + 512 * SP_; R = 400; Rout = SP_; local = blk - 1232; }
    const int C = 512;
    const int c0 = (local & 15) * 32;
    const int r0 = (local >> 4) * 32;

    float* tb = (float*)sm;                 // [32][33]
    const int x = tid & 31, y = tid >> 5;   // 32 x 8
    #pragma unroll
    for (int dd = 0; dd < 32; dd += 8) {
        const int rr = r0 + y + dd, cc = c0 + x;
        tb[(y + dd) * 33 + x] = (rr < R && cc < C) ? I[(size_t)rr * C + cc] : 0.f;
    }
    __syncthreads();
    #pragma unroll
    for (int dd = 0; dd < 32; dd += 8) {
        const int orow = c0 + y + dd;   // original col
        const int ocol = r0 + x;        // original row (output col, may be pad)
        if (orow < C && ocol < Rout)
            O[(size_t)orow * Rout + ocol] = __float2half(ocol < R ? tb[x * 33 + y + dd] : 0.f);
    }
}

// ---------------------------------------------------------------------------
// Scores + masked softmax for one (b, t0..t0+1) row pair (R15 body).
// ---------------------------------------------------------------------------
__device__ void scores_unit(char* sm, int b, int t0, const int* lens,
                            const float* v, float* align_out)
{
    __half2* qsm = (__half2*)sm;               // [2][256]
    __half2* vsm = (__half2*)(sm + 2048);      // [256]
    float*   ssm = (float*)(sm + 3072);        // [2][400]
    float*   red = (float*)(sm + 6272);        // [2][8]

    const __half2* wq = (const __half2*)g_wq_h;
    const __half2* uh = (const __half2*)g_uh_h;
    const int len = lens[b];
    const int tid = threadIdx.x;

    for (int i = tid; i < 2 * (D_ / 2); i += 256)
        qsm[(i >> 8) * 256 + (i & 255)] =
            wq[((size_t)(b * S_ + t0 + (i >> 8))) * (D_ / 2) + (i & 255)];
    for (int i = tid; i < D_ / 2; i += 256)
        vsm[i] = __floats2half2_rn(v[2 * i], v[2 * i + 1]);
    __syncthreads();

    const int warp = tid >> 5, lane = tid & 31;

    // ---- Phase 1: scores for s in [0, len), 32 s per pass (4 per warp) ----
    for (int pass = 0; ; ++pass) {
        const int s0 = pass * 32 + warp * 4;
        if (pass * 32 >= len) break;            // uniform across warps
        if (s0 < len) {
            const __half2* up[4];
            #pragma unroll
            for (int jj = 0; jj < 4; ++jj) {
                int sj = s0 + jj; if (sj > S_ - 1) sj = S_ - 1;
                up[jj] = uh + ((size_t)b * S_ + sj) * (D_ / 2);
            }
            float acc[2][4];
            __half2 acc2[2][4];
            const __half2 h2z = __floats2half2_rn(0.f, 0.f);
            #pragma unroll
            for (int t = 0; t < 2; ++t)
                #pragma unroll
                for (int jj = 0; jj < 4; ++jj) { acc[t][jj] = 0.f; acc2[t][jj] = h2z; }

            #pragma unroll
            for (int i = 0; i < 8; ++i) {
                const int e2 = i * 32 + lane;
                const __half2 v2 = vsm[e2];
                __half2 q2[2];
                q2[0] = qsm[e2];
                q2[1] = qsm[256 + e2];
                #pragma unroll
                for (int jj = 0; jj < 4; ++jj) {
                    const __half2 u2 = __ldg(up[jj] + e2);
                    acc2[0][jj] = __hfma2(v2, tanh2_fast(__hadd2(q2[0], u2)), acc2[0][jj]);
                    acc2[1][jj] = __hfma2(v2, tanh2_fast(__hadd2(q2[1], u2)), acc2[1][jj]);
                }
                if ((i & 3) == 3) {
                    #pragma unroll
                    for (int t = 0; t < 2; ++t)
                        #pragma unroll
                        for (int jj = 0; jj < 4; ++jj) {
                            const float2 f = __half22float2(acc2[t][jj]);
                            acc[t][jj] += f.x + f.y;
                            acc2[t][jj] = h2z;
                        }
                }
            }
            #pragma unroll
            for (int t = 0; t < 2; ++t)
                #pragma unroll
                for (int jj = 0; jj < 4; ++jj) {
                    float a = acc[t][jj];
                    a += __shfl_xor_sync(0xffffffffu, a, 16);
                    a += __shfl_xor_sync(0xffffffffu, a, 8);
                    a += __shfl_xor_sync(0xffffffffu, a, 4);
                    a += __shfl_xor_sync(0xffffffffu, a, 2);
                    a += __shfl_xor_sync(0xffffffffu, a, 1);
                    if (lane == t * 4 + jj && s0 + jj < len)
                        ssm[t * S_ + s0 + jj] = a;
                }
        }
    }
    __syncthreads();

    // ---- Phase 2: masked softmax, 4 warps per row ----
    const int ti = warp >> 2;            // 0..1
    const int wr = warp & 3;             // warp within row
    const int tg = t0 + ti;              // global t
    float vals[4];
    float mx = -1e30f;
    #pragma unroll
    for (int k = 0; k < 4; ++k) {
        const int s = k * 128 + wr * 32 + lane;   // covers 0..511
        const bool ok = (s < len) && (s != tg);
        const float val = ok ? ssm[ti * S_ + s] : -1e30f;
        vals[k] = val;
        mx = fmaxf(mx, val);
    }
    #pragma unroll
    for (int o = 16; o; o >>= 1) mx = fmaxf(mx, __shfl_xor_sync(0xffffffffu, mx, o));
    if (lane == 0) red[ti * 8 + wr] = mx;
    __syncthreads();
    mx = fmaxf(fmaxf(red[ti * 8 + 0], red[ti * 8 + 1]),
               fmaxf(red[ti * 8 + 2], red[ti * 8 + 3]));

    float sum = 0.f;
    #pragma unroll
    for (int k = 0; k < 4; ++k) {
        const float e = (vals[k] > -1e29f) ? __expf(vals[k] - mx) : 0.f;
        vals[k] = e;
        sum += e;
    }
    #pragma unroll
    for (int o = 16; o; o >>= 1) sum += __shfl_xor_sync(0xffffffffu, sum, o);
    if (lane == 0) red[ti * 8 + 4 + wr] = sum;
    __syncthreads();
    const float inv = 1.0f / (red[ti * 8 + 4] + red[ti * 8 + 5] +
                              red[ti * 8 + 6] + red[ti * 8 + 7]);

    const size_t obase  = (size_t)tg * (B_ * S_) + (size_t)b * S_;
    const size_t ohbase = ((size_t)tg * B_ + b) * SP_;
    #pragma unroll
    for (int k = 0; k < 4; ++k) {
        const int s = k * 128 + wr * 32 + lane;
        const float a = vals[k] * inv;
        if (s < S_) {
            align_out[obase + s] = a;
            g_align_h[ohbase + s] = __float2half(a);
        } else if (s < SP_) {
            g_align_h[ohbase + s] = __float2half(0.f);
        }
    }
}

// ---------------------------------------------------------------------------
// Persistent mega-kernel: prep -> gemm1 -> scores+softmax -> ctx -> out,
// separated by grid barriers. 148 CTAs x 256 threads, 1 CTA/SM.
// ---------------------------------------------------------------------------
__global__ void __launch_bounds__(256, 1) mega_kernel(
    const float* __restrict__ input, const float* __restrict__ memory,
    const int* __restrict__ lens,
    const float* __restrict__ Wq, const float* __restrict__ bq,
    const float* __restrict__ Wc, const float* __restrict__ v,
    const float* __restrict__ Wout, const float* __restrict__ bout,
    float* __restrict__ out)
{
    extern __shared__ char sm[];
    __shared__ uint64_t mbars[2];

    const int bid = blockIdx.x, tid = threadIdx.x;
    const uint32_t mb = smem_u32(mbars);
    if (tid < 2) MBAR_INIT(mb + tid * 8, 1);
    __syncthreads();

    // ---- Stage 0: prep ----
    for (int u = bid; u < 1840; u += NBLK) {
        prep_unit(sm, u, input, memory, Wq, Wc, Wout);
        __syncthreads();
    }
    gbar();

    unsigned gcnt = 0;
    int ph[2] = {0, 0};

    // ---- Stage 1: gemm1 (208 tiles): wq_h / uh_h ----
    {
        GemmDesc dq{g_in_h,  g_in_h,  g_WqT, bq,      nullptr, g_wq_h,
                    512, 512, 512, 512, 2, 800, 512, 256, 2};
        GemmDesc du{g_mem_h, g_mem_h, g_WcT, nullptr, nullptr, g_uh_h,
                    512, 512, 512, 512, 2, 800, 512, 256, 2};
        for (int t = bid; t < 208; t += NBLK) {
            const int z = t / 104, rem = t % 104;
            gemm_tile(sm, mb, gcnt, ph, z ? du : dq, (rem >> 3) * 64, (rem & 7) * 64);
        }
    }
    gbar();

    // ---- Stage 2: scores + softmax (400 row pairs) ----
    for (int rp = bid; rp < 400; rp += NBLK) {
        scores_unit(sm, rp / 200, (rp % 200) * 2, lens, v, out + ALIGN_OFF);
        __syncthreads();
    }
    gbar();

    // ---- Stage 3: ctx gemm (112 tiles), K padded to 416 ----
    {
        GemmDesc c0{g_align_h,       g_align_h,       g_memT_h,           nullptr, nullptr, g_ctx_h,
                    B_ * SP_, SP_, SP_, 512, 2, 400, SP_, 208, 2};
        GemmDesc c1{g_align_h + SP_, g_align_h + SP_, g_memT_h + D_ * SP_, nullptr, nullptr, g_ctx_h + S_ * D_,
                    B_ * SP_, SP_, SP_, 512, 2, 400, SP_, 208, 2};
        for (int t = bid; t < 112; t += NBLK) {
            const int z = t / 56, rem = t % 56;
            gemm_tile(sm, mb, gcnt, ph, z ? c1 : c0, (rem >> 3) * 64, (rem & 7) * 64);
        }
    }
    gbar();

    // ---- Stage 4: out gemm (104 tiles) -> [T,B,D] in d_out ----
    {
        GemmDesc go{g_ctx_h, g_in_h, g_WoutT, bout, out, nullptr,
                    512, 512, 1024, 512, 1, 800, 1024, 256, 2};
        for (int t = bid; t < 104; t += NBLK) {
            gemm_tile(sm, mb, gcnt, ph, go, (t >> 3) * 64, (t & 7) * 64);
        }
    }
}

// ---------------------------------------------------------------------------
extern "C" void kernel_launch(void* const* d_in, const int* in_sizes, int n_in,
                              void* d_out, int out_size)
{
    const float* input  = (const float*)d_in[0];
    const float* memory = (const float*)d_in[1];
    const int*   lens   = (const int*)d_in[2];
    const float* Wq     = (const float*)d_in[3];
    const float* bq     = (const float*)d_in[4];
    const float* Wc     = (const float*)d_in[5];
    const float* v      = (const float*)d_in[6];
    const float* Wout   = (const float*)d_in[7];
    const float* bout   = (const float*)d_in[8];
    float* out = (float*)d_out;

    static bool attr_set = false;
    if (!attr_set) {
        cudaFuncSetAttribute(mega_kernel, cudaFuncAttributeMaxDynamicSharedMemorySize,
                             2 * 2 * 64 * (256 + 8) * 2);   // 135168
        attr_set = true;
    }

    mega_kernel<<<NBLK, 256, 2 * 2 * 64 * (256 + 8) * 2>>>(
        input, memory, lens, Wq, bq, Wc, v, Wout, bout, out);
}

// round 17
// speedup vs baseline: 1.3280x; 1.3280x over previous
#include <cuda_runtime.h>
#include <cuda_fp16.h>
#include <cstdint>
#include <cstddef>

// Problem constants
#define B_  2
#define S_  400
#define D_  512
#define ROWS (B_ * S_)                  // 800
#define ALIGN_OFF (S_ * B_ * D_)        // 409600

// Scratch (device globals: no allocation allowed)
__device__ __half g_wq_h[ROWS * D_];
__device__ __half g_uh_h[ROWS * D_];
__device__ __half g_in_h[ROWS * D_];
__device__ __half g_mem_h[ROWS * D_];
__device__ __half g_memT_h[B_ * D_ * S_];      // per b: [512][400]
__device__ __half g_WqT[D_ * D_];              // [n][k]
__device__ __half g_WcT[D_ * D_];
__device__ __half g_WoutT[D_ * 2 * D_];        // [512][1024]
__device__ __half g_ctx_h[ROWS * D_];
__device__ __half g_align_h[S_ * B_ * S_];     // [t][b][s]
__device__ float  g_partial[ROWS * D_];        // input @ Wout[512:] + bout

// ---------------------------------------------------------------------------
__device__ __forceinline__ __half2 tanh2_fast(__half2 x) {
    uint32_t xi = *(uint32_t*)&x, yi;
    asm("tanh.approx.f16x2 %0, %1;" : "=r"(yi) : "r"(xi));
    return *(__half2*)&yi;
}

__device__ __forceinline__ uint32_t smem_u32(const void* p) {
    uint32_t a;
    asm("{ .reg .u64 t; cvta.to.shared.u64 t, %1; cvt.u32.u64 %0, t; }"
        : "=r"(a) : "l"(p));
    return a;
}

#define MBAR_INIT(mbar, cnt) \
    asm volatile("mbarrier.init.shared.b64 [%0], %1;" \
        :: "r"((uint32_t)(mbar)), "r"((uint32_t)(cnt)) : "memory")

#define MBAR_WAIT(mbar, parity) do { \
    uint32_t _m = (uint32_t)(mbar); uint32_t _p = (uint32_t)(parity); uint32_t _d; \
    asm volatile("{\n\t.reg .pred p;\n\t" \
        "mbarrier.try_wait.parity.acquire.cta.shared::cta.b64 p, [%1], %2;\n\t" \
        "selp.b32 %0, 1, 0, p;\n\t}" : "=r"(_d) : "r"(_m), "r"(_p) : "memory"); \
    if (!_d) { \
        asm volatile("{\n\t.reg .pred P1;\n\t" \
            "WL_%=:\n\t" \
            "mbarrier.try_wait.parity.acquire.cta.shared::cta.b64 P1, [%0], %1, 0x989680;\n\t" \
            "@P1 bra.uni WD_%=;\n\t" \
            "bra.uni WL_%=;\n\t" \
            "WD_%=:\n\t}" :: "r"(_m), "r"(_p) : "memory"); \
    } \
} while (0)

__device__ __forceinline__ void bulk_cp(uint32_t dst, const void* src,
                                        uint32_t bytes, uint32_t mbar) {
    asm volatile(
        "cp.async.bulk.shared::cluster.global.mbarrier::complete_tx::bytes "
        "[%0], [%1], %2, [%3];"
        :: "r"(dst), "l"(src), "r"(bytes), "r"(mbar) : "memory");
}

__device__ __forceinline__ void ldsm_x4(uint32_t* r, uint32_t addr) {
    asm volatile("ldmatrix.sync.aligned.m8n8.x4.shared.b16 {%0,%1,%2,%3}, [%4];"
                 : "=r"(r[0]), "=r"(r[1]), "=r"(r[2]), "=r"(r[3]) : "r"(addr));
}

__device__ __forceinline__ void mma16(float* d, const uint32_t* a,
                                      uint32_t b0, uint32_t b1) {
    asm volatile(
        "mma.sync.aligned.m16n8k16.row.col.f32.f16.f16.f32 "
        "{%0,%1,%2,%3}, {%4,%5,%6,%7}, {%8,%9}, {%0,%1,%2,%3};"
        : "+f"(d[0]), "+f"(d[1]), "+f"(d[2]), "+f"(d[3])
        : "r"(a[0]), "r"(a[1]), "r"(a[2]), "r"(a[3]), "r"(b0), "r"(b1));
}

struct GemmArgs {
    const __half* A;      // [M, KA] row-major, lda (halves)
    const __half* A2;     // [M, K-KA] row-major, lda (concat tail)
    const __half* Bt;     // [N, K] row-major, ldb  (B transposed)
    const float*  bias;   // [N] or null
    const float*  addend; // [M,512] row-major f32 or null (added in epilogue)
    float*        C;      // f32 out (omode 0/1)
    __half*       Ch;     // f16 out (omode 2)
};

// ---------------------------------------------------------------------------
// fp16 mma.sync GEMM, 64x64 CTA tile, 256 threads (8 warps: 2M x 4N).
// K staged by KS via cp.async.bulk + mbarrier (R14 config: large stages,
// bufs in {1,2}); ldmatrix.x4 fragments.
// omode 0: C[r*ldc+c] f32; 1: [T,B,D] scatter f32; 2: Ch[r*ldc+c] f16.
// ---------------------------------------------------------------------------
__global__ void __launch_bounds__(256, 1) gemm_f16(
    GemmArgs ga0, GemmArgs ga1, int lda, int KA, int ldb, int ldc,
    int omode, int M, int K, int KS, int bufs)
{
    extern __shared__ __half sh[];
    __shared__ uint64_t mbars[2];

    const GemmArgs g = blockIdx.z ? ga1 : ga0;
    const int tid = threadIdx.x, warp = tid >> 5, lane = tid & 31;
    const int q = lane >> 2, r = lane & 3;
    const int wm = warp >> 2;                  // 0..1 : M offset 32*wm
    const int wn = warp & 3;                   // 0..3 : N offset 16*wn
    const int row0 = blockIdx.y * 64;
    const int col0 = blockIdx.x * 64;
    const int RS = KS + 8;                     // halves per smem row
    const int ns = K / KS;
    const uint32_t shb = smem_u32(sh);
    const uint32_t mb  = smem_u32(mbars);
    const uint32_t boff = (uint32_t)bufs * 64u * (uint32_t)RS;   // halves

    if (tid < 2) MBAR_INIT(mb + tid * 8, 1);
    __syncthreads();

    const int  lrow  = tid & 63;
    const bool isA   = tid < 64;
    const bool isLd  = tid < 128;
    const int  arow_g = row0 + lrow;
    const int  arow_c = (arow_g < M) ? arow_g : (M - 1);
    const uint32_t stage_bytes = (uint32_t)KS * 2u * 128u;

    auto issue = [&](int c) {
        const int bi = c & (bufs - 1);
        const uint32_t mbar = mb + (uint32_t)(c & 1) * 8u;
        if (tid == 0)
            asm volatile("mbarrier.arrive.expect_tx.shared.b64 _, [%0], %1;"
                         :: "r"(mbar), "r"(stage_bytes) : "memory");
        if (isLd) {
            const int k0 = c * KS;
            const __half* src;
            uint32_t dst;
            if (isA) {
                const __half* Ab = (k0 < KA) ? g.A : g.A2;
                const int kk = (k0 < KA) ? k0 : (k0 - KA);
                src = Ab + (size_t)arow_c * lda + kk;
                dst = shb + (uint32_t)((bi * 64 + lrow) * RS) * 2u;
            } else {
                src = g.Bt + (size_t)(col0 + lrow) * ldb + (size_t)c * KS;
                dst = shb + (boff + (uint32_t)((bi * 64 + lrow) * RS)) * 2u;
            }
            bulk_cp(dst, src, (uint32_t)KS * 2u, mbar);
        }
    };

    float acc[2][2][4];
    #pragma unroll
    for (int i = 0; i < 2; ++i)
        #pragma unroll
        for (int j2 = 0; j2 < 2; ++j2)
            #pragma unroll
            for (int k2 = 0; k2 < 4; ++k2) acc[i][j2][k2] = 0.f;

    int ph0 = 0, ph1 = 0;
    issue(0);

    const int j   = lane & 7;
    const int sm8 = (lane >> 3) & 1;
    const int sk8 = (lane >> 4) & 1;

    for (int c = 0; c < ns; ++c) {
        if (c + 1 < ns) issue(c + 1);
        if ((c & 1) == 0) { MBAR_WAIT(mb,     ph0); ph0 ^= 1; }
        else              { MBAR_WAIT(mb + 8, ph1); ph1 ^= 1; }

        const int bi = c & (bufs - 1);
        const uint32_t Ab = shb + (uint32_t)(bi * 64 * RS) * 2u;
        const uint32_t Bb = shb + (boff + (uint32_t)(bi * 64 * RS)) * 2u;
        const int steps = KS >> 4;

        const uint32_t arow_off = (uint32_t)((wm * 32 + j + 8 * sm8) * RS + 8 * sk8) * 2u;
        const uint32_t brow_off = (uint32_t)((wn * 16 + j + 8 * sm8) * RS + 8 * sk8) * 2u;

        for (int s = 0; s < steps; ++s) {
            const uint32_t kb2 = (uint32_t)(s * 16) * 2u;
            uint32_t a0[4], a1[4], bb[4];
            ldsm_x4(a0, Ab + arow_off + kb2);
            ldsm_x4(a1, Ab + arow_off + kb2 + (uint32_t)(16 * RS) * 2u);
            ldsm_x4(bb, Bb + brow_off + kb2);
            mma16(acc[0][0], a0, bb[0], bb[2]);
            mma16(acc[0][1], a0, bb[1], bb[3]);
            mma16(acc[1][0], a1, bb[0], bb[2]);
            mma16(acc[1][1], a1, bb[1], bb[3]);
        }
        __syncthreads();
    }

    // ---- epilogue ----
    float bv[2][2];
    #pragma unroll
    for (int nt = 0; nt < 2; ++nt) {
        const int cc = col0 + wn * 16 + nt * 8 + r * 2;
        bv[nt][0] = g.bias ? __ldg(g.bias + cc)     : 0.f;
        bv[nt][1] = g.bias ? __ldg(g.bias + cc + 1) : 0.f;
    }
    #pragma unroll
    for (int mt = 0; mt < 2; ++mt) {
        #pragma unroll
        for (int rh = 0; rh < 2; ++rh) {
            const int rr = row0 + wm * 32 + mt * 16 + rh * 8 + q;
            if (rr >= M) continue;
            #pragma unroll
            for (int nt = 0; nt < 2; ++nt) {
                const int cc = col0 + wn * 16 + nt * 8 + r * 2;
                float ox = acc[mt][nt][rh * 2 + 0] + bv[nt][0];
                float oy = acc[mt][nt][rh * 2 + 1] + bv[nt][1];
                if (g.addend) {
                    const float2 ad = *(const float2*)(g.addend + (size_t)rr * D_ + cc);
                    ox += ad.x;
                    oy += ad.y;
                }
                if (omode == 2) {
                    __half2* dp = (__half2*)(g.Ch + (size_t)rr * ldc + cc);
                    *dp = __floats2half2_rn(ox, oy);
                } else {
                    float* rowp;
                    if (omode == 0) rowp = g.C + (size_t)rr * ldc;
                    else {
                        const int t = rr % S_, bbn = rr / S_;
                        rowp = g.C + (size_t)t * (B_ * D_) + (size_t)bbn * D_;
                    }
                    *(float2*)(rowp + cc) = make_float2(ox, oy);
                }
            }
        }
    }
}

// ---------------------------------------------------------------------------
// Shared transpose helper (32x32 tile, f32 -> f16)
// ---------------------------------------------------------------------------
__device__ __forceinline__ void trans_tile(const float* I, __half* O,
                                           int R, int C, int local)
{
    __shared__ float t[32][33];
    const int tid = threadIdx.x;
    const int c0 = (local & 15) * 32;
    const int r0 = (local >> 4) * 32;
    const int x = tid & 31, y = tid >> 5;    // 32 x 8
    #pragma unroll
    for (int d = 0; d < 32; d += 8) {
        const int rr = r0 + y + d, cc = c0 + x;
        t[y + d][x] = (rr < R && cc < C) ? I[(size_t)rr * C + cc] : 0.f;
    }
    __syncthreads();
    #pragma unroll
    for (int d = 0; d < 32; d += 8) {
        const int orow = c0 + y + d;   // original col
        const int ocol = r0 + x;       // original row
        if (orow < C && ocol < R)
            O[(size_t)orow * R + ocol] = __float2half(t[x][y + d]);
    }
}

// ---------------------------------------------------------------------------
// prep_early: [0,256) Wq^T, [256,512) Wc^T, [512,912) f32->f16 conversions.
// ---------------------------------------------------------------------------
__global__ void __launch_bounds__(256) prep_early(
    const float* __restrict__ input, const float* __restrict__ memory,
    const float* __restrict__ Wq, const float* __restrict__ Wc)
{
    const int blk = blockIdx.x, tid = threadIdx.x;
    if (blk >= 512) {
        const int i = (blk - 512) * 256 + tid;       // < 102400
        float4 v = ((const float4*)input)[i];
        ((__half2*)g_in_h)[2 * i]     = __floats2half2_rn(v.x, v.y);
        ((__half2*)g_in_h)[2 * i + 1] = __floats2half2_rn(v.z, v.w);
        v = ((const float4*)memory)[i];
        ((__half2*)g_mem_h)[2 * i]     = __floats2half2_rn(v.x, v.y);
        ((__half2*)g_mem_h)[2 * i + 1] = __floats2half2_rn(v.z, v.w);
        return;
    }
    if (blk < 256) trans_tile(Wq, g_WqT, 512, 512, blk);
    else           trans_tile(Wc, g_WcT, 512, 512, blk - 256);
}

// ---------------------------------------------------------------------------
// prep_late: [0,512) Wout^T, [512,720) mem b0 ^T, [720,928) mem b1 ^T.
// ---------------------------------------------------------------------------
__global__ void __launch_bounds__(256) prep_late(
    const float* __restrict__ memory, const float* __restrict__ Wout)
{
    const int blk = blockIdx.x;
    if (blk < 512)      trans_tile(Wout, g_WoutT, 1024, 512, blk);
    else if (blk < 720) trans_tile(memory, g_memT_h, 400, 512, blk - 512);
    else                trans_tile(memory + 400 * 512, g_memT_h + 512 * 400,
                                   400, 512, blk - 720);
}

// ---------------------------------------------------------------------------
// FUSED scores + masked softmax (R14 body).
// CTA = 2 t-rows x full s-range. grid (200, 2), 256 threads (8 warps).
// ---------------------------------------------------------------------------
__global__ void __launch_bounds__(256) scores_softmax_kernel(
    const __half2* __restrict__ wq, const __half2* __restrict__ uh,
    const float* __restrict__ v, const int* __restrict__ lens,
    float* __restrict__ align_out, __half* __restrict__ align_h)
{
    const int b = blockIdx.y;
    const int t0 = blockIdx.x * 2;
    const int len = lens[b];

    __shared__ __half2 qsm[2][D_ / 2];
    __shared__ __half2 vsm[D_ / 2];
    __shared__ float   ssm[2][S_];
    __shared__ float   red[2][8];

    const int tid = threadIdx.x;
    for (int i = tid; i < 2 * (D_ / 2); i += 256)
        qsm[i >> 8][i & 255] = wq[((size_t)(b * S_ + t0 + (i >> 8))) * (D_ / 2) + (i & 255)];
    for (int i = tid; i < D_ / 2; i += 256)
        vsm[i] = __floats2half2_rn(v[2 * i], v[2 * i + 1]);
    __syncthreads();

    const int warp = tid >> 5, lane = tid & 31;

    for (int pass = 0; ; ++pass) {
        const int s0 = pass * 32 + warp * 4;
        if (pass * 32 >= len) break;            // uniform across warps
        if (s0 < len) {
            const __half2* up[4];
            #pragma unroll
            for (int j = 0; j < 4; ++j) {
                int sj = s0 + j; if (sj > S_ - 1) sj = S_ - 1;
                up[j] = uh + ((size_t)b * S_ + sj) * (D_ / 2);
            }
            float acc[2][4];
            __half2 acc2[2][4];
            const __half2 h2z = __floats2half2_rn(0.f, 0.f);
            #pragma unroll
            for (int t = 0; t < 2; ++t)
                #pragma unroll
                for (int j = 0; j < 4; ++j) { acc[t][j] = 0.f; acc2[t][j] = h2z; }

            #pragma unroll
            for (int i = 0; i < 8; ++i) {
                const int e2 = i * 32 + lane;
                const __half2 v2 = vsm[e2];
                __half2 q2[2];
                q2[0] = qsm[0][e2];
                q2[1] = qsm[1][e2];
                #pragma unroll
                for (int j = 0; j < 4; ++j) {
                    const __half2 u2 = __ldg(up[j] + e2);
                    acc2[0][j] = __hfma2(v2, tanh2_fast(__hadd2(q2[0], u2)), acc2[0][j]);
                    acc2[1][j] = __hfma2(v2, tanh2_fast(__hadd2(q2[1], u2)), acc2[1][j]);
                }
                if ((i & 3) == 3) {
                    #pragma unroll
                    for (int t = 0; t < 2; ++t)
                        #pragma unroll
                        for (int j = 0; j < 4; ++j) {
                            const float2 f = __half22float2(acc2[t][j]);
                            acc[t][j] += f.x + f.y;
                            acc2[t][j] = h2z;
                        }
                }
            }
            #pragma unroll
            for (int t = 0; t < 2; ++t)
                #pragma unroll
                for (int j = 0; j < 4; ++j) {
                    float a = acc[t][j];
                    a += __shfl_xor_sync(0xffffffffu, a, 16);
                    a += __shfl_xor_sync(0xffffffffu, a, 8);
                    a += __shfl_xor_sync(0xffffffffu, a, 4);
                    a += __shfl_xor_sync(0xffffffffu, a, 2);
                    a += __shfl_xor_sync(0xffffffffu, a, 1);
                    if (lane == t * 4 + j && s0 + j < len)
                        ssm[t][s0 + j] = a;
                }
        }
    }
    __syncthreads();

    const int ti = warp >> 2;
    const int wr = warp & 3;
    const int tg = t0 + ti;
    float vals[4];
    float mx = -1e30f;
    #pragma unroll
    for (int k = 0; k < 4; ++k) {
        const int s = k * 128 + wr * 32 + lane;
        const bool ok = (s < len) && (s != tg);
        const float val = ok ? ssm[ti][s] : -1e30f;
        vals[k] = val;
        mx = fmaxf(mx, val);
    }
    #pragma unroll
    for (int o = 16; o; o >>= 1) mx = fmaxf(mx, __shfl_xor_sync(0xffffffffu, mx, o));
    if (lane == 0) red[ti][wr] = mx;
    __syncthreads();
    mx = fmaxf(fmaxf(red[ti][0], red[ti][1]), fmaxf(red[ti][2], red[ti][3]));

    float sum = 0.f;
    #pragma unroll
    for (int k = 0; k < 4; ++k) {
        const float e = (vals[k] > -1e29f) ? __expf(vals[k] - mx) : 0.f;
        vals[k] = e;
        sum += e;
    }
    #pragma unroll
    for (int o = 16; o; o >>= 1) sum += __shfl_xor_sync(0xffffffffu, sum, o);
    if (lane == 0) red[ti][4 + wr] = sum;
    __syncthreads();
    const float inv = 1.0f / (red[ti][4] + red[ti][5] + red[ti][6] + red[ti][7]);

    const size_t obase = (size_t)tg * (B_ * S_) + (size_t)b * S_;
    #pragma unroll
    for (int k = 0; k < 4; ++k) {
        const int s = k * 128 + wr * 32 + lane;
        if (s < S_) {
            const float a = vals[k] * inv;
            align_out[obase + s] = a;
            align_h[obase + s]   = __float2half(a);
        }
    }
}

// ---------------------------------------------------------------------------
extern "C" void kernel_launch(void* const* d_in, const int* in_sizes, int n_in,
                              void* d_out, int out_size)
{
    const float* input  = (const float*)d_in[0];
    const float* memory = (const float*)d_in[1];
    const int*   lens   = (const int*)d_in[2];
    const float* Wq     = (const float*)d_in[3];
    const float* bq     = (const float*)d_in[4];
    const float* Wc     = (const float*)d_in[5];
    const float* v      = (const float*)d_in[6];
    const float* Wout   = (const float*)d_in[7];
    const float* bout   = (const float*)d_in[8];
    float* out = (float*)d_out;

    __half *wq_h, *uh_h, *in_h, *mem_h, *memT_h, *WqT, *WcT, *WoutT, *ctx_h, *align_h;
    float *partial;
    cudaGetSymbolAddress((void**)&wq_h,    g_wq_h);
    cudaGetSymbolAddress((void**)&uh_h,    g_uh_h);
    cudaGetSymbolAddress((void**)&in_h,    g_in_h);
    cudaGetSymbolAddress((void**)&mem_h,   g_mem_h);
    cudaGetSymbolAddress((void**)&memT_h,  g_memT_h);
    cudaGetSymbolAddress((void**)&WqT,     g_WqT);
    cudaGetSymbolAddress((void**)&WcT,     g_WcT);
    cudaGetSymbolAddress((void**)&WoutT,   g_WoutT);
    cudaGetSymbolAddress((void**)&ctx_h,   g_ctx_h);
    cudaGetSymbolAddress((void**)&align_h, g_align_h);
    cudaGetSymbolAddress((void**)&partial, g_partial);

    static cudaStream_t s2 = nullptr;
    static cudaEvent_t evF = nullptr, evJ = nullptr;
    static bool inited = false;
    if (!inited) {
        cudaFuncSetAttribute(gemm_f16, cudaFuncAttributeMaxDynamicSharedMemorySize,
                             2 * 2 * 64 * (256 + 8) * 2);   // 135168
        cudaStreamCreateWithFlags(&s2, cudaStreamNonBlocking);
        cudaEventCreateWithFlags(&evF, cudaEventDisableTiming);
        cudaEventCreateWithFlags(&evJ, cudaEventDisableTiming);
        inited = true;
    }

    // ---- main stream: prep_early (WqT, WcT, in_h, mem_h) ----
    prep_early<<<912, 256>>>(input, memory, Wq, Wc);

    // ---- fork side stream: prep_late + out_partial ----
    cudaEventRecord(evF, 0);
    cudaStreamWaitEvent(s2, evF, 0);
    prep_late<<<928, 256, 0, s2>>>(memory, Wout);
    {
        // partial = in_h @ WoutT[:,512:] + bout   -> f32 [800,512]
        GemmArgs gp{in_h, in_h, WoutT + 512, bout, nullptr, partial, nullptr};
        gemm_f16<<<dim3(8, 13, 1), 256, 2 * 2 * 64 * 264 * 2, s2>>>(
            gp, gp, 512, 512, 1024, 512, 0, 800, 512, 256, 2);
    }
    cudaEventRecord(evJ, s2);

    // ---- main stream: gemm1 (wq_h / uh_h) ----
    {
        GemmArgs gq{in_h,  in_h,  WqT, bq,      nullptr, nullptr, wq_h};
        GemmArgs gu{mem_h, mem_h, WcT, nullptr, nullptr, nullptr, uh_h};
        gemm_f16<<<dim3(8, 13, 2), 256, 2 * 2 * 64 * 264 * 2>>>(
            gq, gu, 512, 512, 512, 512, 2, 800, 512, 256, 2);
    }
    // ---- main stream: fused scores + softmax ----
    scores_softmax_kernel<<<dim3(200, 2), 256>>>(
        (const __half2*)wq_h, (const __half2*)uh_h, v, lens,
        out + ALIGN_OFF, align_h);

    // ---- join: need memT (prep_late) for ctx, partial for out ----
    cudaStreamWaitEvent(0, evJ, 0);

    // ---- ctx: c[b] = align[b] @ memory[b] -> ctx_h (f16), K=400 single stage
    {
        GemmArgs c0{align_h,       align_h,       memT_h,             nullptr, nullptr, nullptr, ctx_h};
        GemmArgs c1{align_h + S_,  align_h + S_,  memT_h + D_ * S_,   nullptr, nullptr, nullptr, ctx_h + S_ * D_};
        gemm_f16<<<dim3(8, 7, 2), 256, 1 * 2 * 64 * 408 * 2>>>(
            c0, c1, 800, 400, 400, 512, 2, 400, 400, 400, 1);
    }
    // ---- out: attn_h = ctx @ WoutT[:,0:512] + partial -> [T,B,D] in d_out
    {
        GemmArgs go{ctx_h, ctx_h, WoutT, nullptr, partial, out, nullptr};
        gemm_f16<<<dim3(8, 13, 1), 256, 2 * 2 * 64 * 264 * 2>>>(
            go, go, 512, 512, 1024, 512, 1, 800, 512, 256, 2);
    }
}